// round 8
// baseline (speedup 1.0000x reference)
#include <cuda_runtime.h>
#include <cuda_bf16.h>
#include <cstdint>
#include <math.h>

#define Bn 32
#define Tn 2048
#define Dn 512
#define ZB 32
#define SPLIT 32
#define SEG 8
#define NIT (Tn / 32)

#define NT 16              // 16x16 tiles of 32x32
#define NTILE (NT * (NT + 1) / 2)   // 136 lower tiles

// ---------------- static scratch ----------------
__device__ float g_pmean[SEG][Bn][Dn];
__device__ float g_bmean[Bn][Dn];
__device__ float g_gmean[Dn];
__device__ __nv_bfloat16 g_xcb[(size_t)Bn * Tn * Dn];
__device__ float g_Gpart[SPLIT][Dn * Dn];
__device__ float g_C[Dn * Dn];                 // L (lower tiles valid)
__device__ unsigned g_flag[NT * NT * 32];      // 128B-padded tile-done flags

__device__ __forceinline__ uint32_t smem_u32(const void* p) {
    return (uint32_t)__cvta_generic_to_shared(p);
}

// ---------------- 1) fused partial means + bf16 convert ---------------------
__global__ void conv_mean(const float* __restrict__ x) {
    int b   = blockIdx.y;
    int seg = blockIdx.z;
    int d   = blockIdx.x * 128 + threadIdx.x;
    size_t base = ((size_t)b * Tn + (size_t)seg * (Tn / SEG)) * Dn + d;
    float s = 0.f;
#pragma unroll 4
    for (int t = 0; t < Tn / SEG; t++) {
        float f = x[base + (size_t)t * Dn];
        s += f;
        g_xcb[base + (size_t)t * Dn] = __float2bfloat16_rn(f);
    }
    g_pmean[seg][b][d] = s;
}

// one block, 512 threads: finish means + zero tile flags (each replay)
__global__ void __launch_bounds__(512) mean_fuse() {
    int d = threadIdx.x;
    for (int l = d; l < NT * NT * 32; l += 512) g_flag[l] = 0u;
    float gsum = 0.f;
#pragma unroll
    for (int b = 0; b < Bn; b++) {
        float s = 0.f;
#pragma unroll
        for (int g = 0; g < SEG; g++) s += g_pmean[g][b][d];
        float bm = s * (1.0f / (float)Tn);
        g_bmean[b][d] = bm;
        gsum += bm;
    }
    g_gmean[d] = gsum * (1.0f / (float)Bn);
}

// ---------------- 2) tensor-core Gram (validated, unchanged) ----------------
__global__ void __launch_bounds__(256) gram_mma(const __nv_bfloat16* __restrict__ xb) {
    if (blockIdx.y > blockIdx.x) return;
    int dtile = blockIdx.x * 128;
    int etile = blockIdx.y * 128;
    int bz    = blockIdx.z;

    __shared__ __nv_bfloat16 As[2][32][128];
    __shared__ __nv_bfloat16 Bs[2][32][128];

    int tid  = threadIdx.x;
    int lane = tid & 31;
    int warp = tid >> 5;
    int m0 = (warp >> 2) * 64;
    int n0 = (warp & 3) * 32;

    const __nv_bfloat16* xbase = xb + (size_t)bz * Tn * Dn;

    float acc[4][4][4];
#pragma unroll
    for (int a = 0; a < 4; a++)
#pragma unroll
        for (int b = 0; b < 4; b++)
#pragma unroll
            for (int c = 0; c < 4; c++) acc[a][b][c] = 0.f;

    auto issue = [&](int it, int stg) {
#pragma unroll
        for (int rep = 0; rep < 2; rep++) {
            int l    = tid + rep * 256;
            int row  = l >> 4;
            int ch   = l & 15;
            int chs  = ch ^ (row & 7);
            const __nv_bfloat16* gA = xbase + (size_t)(it * 32 + row) * Dn + dtile + ch * 8;
            const __nv_bfloat16* gB = xbase + (size_t)(it * 32 + row) * Dn + etile + ch * 8;
            uint32_t sA = smem_u32(&As[stg][row][chs * 8]);
            uint32_t sB = smem_u32(&Bs[stg][row][chs * 8]);
            asm volatile("cp.async.cg.shared.global [%0], [%1], 16;" :: "r"(sA), "l"(gA));
            asm volatile("cp.async.cg.shared.global [%0], [%1], 16;" :: "r"(sB), "l"(gB));
        }
    };

    issue(0, 0);
    asm volatile("cp.async.commit_group;");

    for (int it = 0; it < NIT; it++) {
        if (it + 1 < NIT) {
            issue(it + 1, (it + 1) & 1);
            asm volatile("cp.async.commit_group;");
            asm volatile("cp.async.wait_group 1;");
        } else {
            asm volatile("cp.async.wait_group 0;");
        }
        __syncthreads();
        int stg = it & 1;

#pragma unroll
        for (int ks = 0; ks < 2; ks++) {
            uint32_t a[4][4];
            uint32_t bfr[2][4];
#pragma unroll
            for (int mi = 0; mi < 4; mi++) {
                int krow = ks * 16 + (lane & 7) + ((lane & 16) ? 8 : 0);
                int ch   = (m0 >> 3) + mi * 2 + ((lane >> 3) & 1);
                int chs  = ch ^ (krow & 7);
                uint32_t addr = smem_u32(&As[stg][krow][chs * 8]);
                asm volatile("ldmatrix.sync.aligned.m8n8.x4.trans.shared.b16 {%0,%1,%2,%3}, [%4];"
                             : "=r"(a[mi][0]), "=r"(a[mi][1]), "=r"(a[mi][2]), "=r"(a[mi][3])
                             : "r"(addr));
            }
#pragma unroll
            for (int pb = 0; pb < 2; pb++) {
                int krow = ks * 16 + (lane & 7) + ((lane & 8) ? 8 : 0);
                int ch   = (n0 >> 3) + pb * 2 + ((lane >> 4) & 1);
                int chs  = ch ^ (krow & 7);
                uint32_t addr = smem_u32(&Bs[stg][krow][chs * 8]);
                asm volatile("ldmatrix.sync.aligned.m8n8.x4.trans.shared.b16 {%0,%1,%2,%3}, [%4];"
                             : "=r"(bfr[pb][0]), "=r"(bfr[pb][1]), "=r"(bfr[pb][2]), "=r"(bfr[pb][3])
                             : "r"(addr));
            }
#pragma unroll
            for (int mi = 0; mi < 4; mi++)
#pragma unroll
                for (int nb = 0; nb < 4; nb++) {
                    uint32_t b0 = bfr[nb >> 1][(nb & 1) * 2];
                    uint32_t b1 = bfr[nb >> 1][(nb & 1) * 2 + 1];
                    asm volatile(
                        "mma.sync.aligned.m16n8k16.row.col.f32.bf16.bf16.f32 "
                        "{%0,%1,%2,%3}, {%4,%5,%6,%7}, {%8,%9}, {%0,%1,%2,%3};"
                        : "+f"(acc[mi][nb][0]), "+f"(acc[mi][nb][1]),
                          "+f"(acc[mi][nb][2]), "+f"(acc[mi][nb][3])
                        : "r"(a[mi][0]), "r"(a[mi][1]), "r"(a[mi][2]), "r"(a[mi][3]),
                          "r"(b0), "r"(b1));
                }
        }
        __syncthreads();
    }

    float* gp = g_Gpart[bz];
    int g  = lane >> 2;
    int tg = lane & 3;
#pragma unroll
    for (int mi = 0; mi < 4; mi++)
#pragma unroll
        for (int nb = 0; nb < 4; nb++) {
            int row = dtile + m0 + mi * 16 + g;
            int col = etile + n0 + nb * 8 + tg * 2;
            *(float2*)&gp[(size_t)row * Dn + col]       = make_float2(acc[mi][nb][0], acc[mi][nb][1]);
            *(float2*)&gp[(size_t)(row + 8) * Dn + col] = make_float2(acc[mi][nb][2], acc[mi][nb][3]);
        }
}

// ---------------- flag helpers ----------------------------------------------
__device__ __forceinline__ void flag_wait(int i, int j) {
    unsigned* f = &g_flag[(i * NT + j) * 32];
    unsigned v;
    while (true) {
        asm volatile("ld.relaxed.gpu.u32 %0, [%1];" : "=r"(v) : "l"(f) : "memory");
        if (v) break;
        __nanosleep(64);
    }
    asm volatile("fence.acq_rel.gpu;" ::: "memory");
}
__device__ __forceinline__ void flag_set(int i, int j) {
    unsigned* f = &g_flag[(i * NT + j) * 32];
    asm volatile("fence.acq_rel.gpu;" ::: "memory");
    asm volatile("st.relaxed.gpu.u32 [%0], 1;" :: "l"(f) : "memory");
}

// ---------------- warp-shuffle 32x32 Cholesky factor (stride-33 smem) -------
__device__ __forceinline__ void factor32_warp(float* s, int lane) {
    float a[32];
#pragma unroll
    for (int i = 0; i < 32; i++) a[i] = (i >= lane) ? s[i * 33 + lane] : 0.f;
#pragma unroll
    for (int j = 0; j < 32; j++) {
        float pivot = __shfl_sync(0xffffffffu, a[j], j);
        float rinv  = 1.0f / sqrtf(pivot);
        float lej = 0.f;
#pragma unroll
        for (int i = 0; i < 32; i++) {
            float lij = __shfl_sync(0xffffffffu, a[i], j) * rinv;
            if (i == lane) lej = lij;
            if (lane == j) a[i] = lij;
            else if (lane > j && i >= lane) a[i] -= lij * lej;
        }
    }
#pragma unroll
    for (int i = 0; i < 32; i++)
        if (i >= lane) s[i * 33 + lane] = a[i];
}

// ---------------- 3) dataflow tile Cholesky ---------------------------------
// One block per lower 32x32 tile (i,j). Left-looking:
//   Acc = cov(i,j);  for k<j: Acc -= L(i,k) L(j,k)^T;  then trsm / factor.
__global__ void __launch_bounds__(256) chol_tiles() {
    __shared__ float Acc[32 * 33];
    __shared__ float Lk1[32 * 33];
    __shared__ float Lk2[32 * 33];

    int bid = blockIdx.x, tid = threadIdx.x;
    int ti = 0;
    while ((ti + 1) * (ti + 2) / 2 <= bid) ti++;
    int tj = bid - ti * (ti + 1) / 2;          // tile (ti, tj), tj <= ti

    int r  = tid >> 3;            // 0..31 row
    int cb = (tid & 3) * 8 + ((tid >> 2) & 1) * 4;  // no — keep simple below
    cb = (tid & 7) * 4;           // 4 consecutive cols per thread

    // ---- cov tile init: stage means, then acc regs ----
    for (int l = tid; l < Bn * 32; l += 256) {
        int b = l >> 5, rr = l & 31;
        Lk1[b * 33 + rr] = g_bmean[b][ti * 32 + rr];
        Lk2[b * 33 + rr] = g_bmean[b][tj * 32 + rr];
    }
    __syncthreads();

    float acc[4];
    {
        const float inv = 1.0f / ((float)(Tn - 1) * (float)Bn);
#pragma unroll
        for (int c = 0; c < 4; c++) {
            float mk = 0.f;
#pragma unroll
            for (int b = 0; b < Bn; b++) mk += Lk1[b * 33 + r] * Lk2[b * 33 + cb + c];
            float gs = 0.f;
            size_t gidx = (size_t)(ti * 32 + r) * Dn + tj * 32 + cb + c;
#pragma unroll
            for (int g = 0; g < SPLIT; g++) gs += g_Gpart[g][gidx];
            acc[c] = (gs - (float)Tn * mk) * inv;
        }
    }
    __syncthreads();

    // ---- left-looking updates: Acc -= L(ti,k) L(tj,k)^T ----
    for (int k = 0; k < tj; k++) {
        if (tid == 0) flag_wait(ti, k);
        if (tid == 32 && ti != tj) flag_wait(tj, k);
        __syncthreads();
        for (int l = tid; l < 1024; l += 256) {
            int rr = l >> 5, cc = l & 31;
            Lk1[rr * 33 + cc] = g_C[(size_t)(ti * 32 + rr) * Dn + k * 32 + cc];
            if (ti != tj)
                Lk2[rr * 33 + cc] = g_C[(size_t)(tj * 32 + rr) * Dn + k * 32 + cc];
        }
        __syncthreads();
        const float* Rj = (ti != tj) ? Lk2 : Lk1;
#pragma unroll 8
        for (int m = 0; m < 32; m++) {
            float a = Lk1[r * 33 + m];
#pragma unroll
            for (int c = 0; c < 4; c++) acc[c] -= a * Rj[(cb + c) * 33 + m];
        }
        __syncthreads();
    }

    if (ti == tj) {
        // ---- diagonal: factor ----
#pragma unroll
        for (int c = 0; c < 4; c++) Acc[r * 33 + cb + c] = acc[c];
        __syncthreads();
        if (tid < 32) factor32_warp(Acc, tid);
        __syncthreads();
        for (int l = tid; l < 1024; l += 256) {
            int rr = l >> 5, cc = l & 31;
            if (cc <= rr) g_C[(size_t)(ti * 32 + rr) * Dn + ti * 32 + cc] = Acc[rr * 33 + cc];
        }
        __syncthreads();
        if (tid == 0) flag_set(ti, ti);
    } else {
        // ---- off-diagonal: wait diag, trsm X * Ljj^T = Acc ----
        if (tid == 0) flag_wait(tj, tj);
        __syncthreads();
        for (int l = tid; l < 1024; l += 256) {
            int rr = l >> 5, cc = l & 31;
            Lk1[rr * 33 + cc] = (cc <= rr) ? g_C[(size_t)(tj * 32 + rr) * Dn + tj * 32 + cc] : 0.f;
        }
#pragma unroll
        for (int c = 0; c < 4; c++) Acc[r * 33 + cb + c] = acc[c];
        __syncthreads();

        // 8 warps x 4 rows, lane = column; serial chain over 32 columns
        int lane = tid & 31, w = tid >> 5;
        float ar[4];
#pragma unroll
        for (int q = 0; q < 4; q++) ar[q] = Acc[(w * 4 + q) * 33 + lane];
        float rinv = 1.0f / Lk1[lane * 33 + lane];
        float lrow_c;
#pragma unroll
        for (int c = 0; c < 32; c++) {
            float rc = __shfl_sync(0xffffffffu, rinv, c);
            lrow_c = Lk1[lane * 33 + c];     // Ljj[lane][c]
#pragma unroll
            for (int q = 0; q < 4; q++) {
                float xv = __shfl_sync(0xffffffffu, ar[q], c) * rc;
                if (lane == c)      ar[q] = xv;
                else if (lane > c)  ar[q] -= xv * lrow_c;
            }
        }
#pragma unroll
        for (int q = 0; q < 4; q++)
            g_C[(size_t)(ti * 32 + w * 4 + q) * Dn + tj * 32 + lane] = ar[q];
        __syncthreads();
        if (tid == 0) flag_set(ti, tj);
    }
}

// ---------------- 4) output: out[s][d] = gmean[d] + sum_{e<=d} z[s][e]L[d][e]
// warp handles one d (lane = sample s) -> L row broadcast, fully parallel
__global__ void __launch_bounds__(256) out_kernel(const float* __restrict__ z,
                                                 float* __restrict__ out) {
    int lane = threadIdx.x & 31;          // sample s
    int d    = blockIdx.x * 8 + (threadIdx.x >> 5);
    float acc = g_gmean[d];
    const float* Crow = g_C + (size_t)d * Dn;
    const float* zr   = z + (size_t)lane * Dn;
    for (int e = 0; e <= d; e++) acc += zr[e] * Crow[e];
    out[(size_t)lane * Dn + d] = acc;
}

// ---------------- launch -----------------------------------------------------
extern "C" void kernel_launch(void* const* d_in, const int* in_sizes, int n_in,
                              void* d_out, int out_size) {
    const float* x = (const float*)d_in[0];
    const float* z = (const float*)d_in[1];
    if (in_sizes[0] != Bn * Tn * Dn) { x = (const float*)d_in[1]; z = (const float*)d_in[0]; }
    float* out = (float*)d_out;

    conv_mean<<<dim3(4, Bn, SEG), 128>>>(x);
    mean_fuse<<<1, 512>>>();

    __nv_bfloat16* xcb;
    cudaGetSymbolAddress((void**)&xcb, g_xcb);
    gram_mma<<<dim3(4, 4, SPLIT), 256>>>(xcb);

    chol_tiles<<<NTILE, 256>>>();

    out_kernel<<<Dn / 8, 256>>>(z, out);
}